// round 8
// baseline (speedup 1.0000x reference)
#include <cuda_runtime.h>
#include <cuda_bf16.h>
#include <math.h>

#define B_TOT 4096
#define T_LEN 32
#define DDIM 15
#define NSTEPS 5
#define DT_C 0.2f
#define RPB 8
#define NBLK (B_TOT / RPB)
#define PAD 12

typedef unsigned long long ull;
typedef unsigned int u32;

// ---------------- packed f32x2 helpers ------------------------------------------
__device__ __forceinline__ void fma2(ull& acc, ull a, ull b) {
    asm("fma.rn.f32x2 %0, %1, %2, %0;" : "+l"(acc) : "l"(a), "l"(b));
}
__device__ __forceinline__ ull pack2f(float w) {
    ull r; asm("mov.b64 %0, {%1, %1};" : "=l"(r) : "r"(__float_as_uint(w))); return r;
}
__device__ __forceinline__ ull bplo(u32 u) {
    u32 f = u << 16; ull r; asm("mov.b64 %0, {%1, %1};" : "=l"(r) : "r"(f)); return r;
}
__device__ __forceinline__ ull bphi(u32 u) {
    u32 f = u & 0xFFFF0000u; ull r; asm("mov.b64 %0, {%1, %1};" : "=l"(r) : "r"(f)); return r;
}
__device__ __forceinline__ float2 unpack2(ull v) {
    float2 f; asm("mov.b64 {%0, %1}, %2;" : "=f"(f.x), "=f"(f.y) : "l"(v)); return f;
}
__device__ __forceinline__ float fsig(float x) { return 1.f / (1.f + __expf(-x)); }
__device__ __forceinline__ float ftanh(float x) { return 1.f - 2.f / (1.f + __expf(2.f * x)); }

// ---------------- weight scratch (device globals) -------------------------------
__device__ u32 g_Wih_rz[26 * 128];
__device__ u32 g_Wih_g[13 * 128];
__device__ u32 g_Whh_rz[128 * 128];
__device__ u32 g_Whh_g[64 * 128];
__device__ u32 g_dr0C[32 * 128];
__device__ u32 g_dr0D[13 * 128];
__device__ u32 g_df0C[32 * 128];
__device__ u32 g_df0D[13 * 128];
__device__ u32 g_dr1P[64 * 128];
__device__ u32 g_dr2P[64 * 128];
__device__ u32 g_df1P[64 * 128];
__device__ float g_dr3T[128 * 15];
__device__ float g_df2T[128 * 15];
__device__ float g_projT[128 * 64];

__device__ __forceinline__ u32 bfbits(float w) {
    __nv_bfloat16 h = __float2bfloat16(w);
    return (u32)__bfloat16_as_ushort(h);
}

// ---------------- prep: repack/quantize weights ---------------------------------
__global__ void prep_kernel(const float* __restrict__ wih, const float* __restrict__ whh,
                            const float* __restrict__ proj,
                            const float* __restrict__ d0, const float* __restrict__ d1,
                            const float* __restrict__ d2, const float* __restrict__ d3,
                            const float* __restrict__ f0, const float* __restrict__ f1,
                            const float* __restrict__ f2) {
    int tid = blockIdx.x * blockDim.x + threadIdx.x;
    int nt = gridDim.x * blockDim.x;
    for (int i = tid; i < 26 * 128; i += nt) {
        int k = i >> 7, j = i & 127;
        float wr = (k < 25) ? wih[j * 25 + k] : 0.f;
        float wz = (k < 25) ? wih[(128 + j) * 25 + k] : 0.f;
        g_Wih_rz[i] = bfbits(wr) | (bfbits(wz) << 16);
    }
    for (int i = tid; i < 13 * 128; i += nt) {
        int kp = i >> 7, j = i & 127;
        int k0 = 2 * kp, k1 = 2 * kp + 1;
        float g0 = (k0 < 25) ? wih[(256 + j) * 25 + k0] : 0.f;
        float g1 = (k1 < 25) ? wih[(256 + j) * 25 + k1] : 0.f;
        g_Wih_g[i] = bfbits(g0) | (bfbits(g1) << 16);
    }
    for (int i = tid; i < 128 * 128; i += nt) {
        int k = i >> 7, j = i & 127;
        g_Whh_rz[i] = bfbits(whh[j * 128 + k]) | (bfbits(whh[(128 + j) * 128 + k]) << 16);
    }
    for (int i = tid; i < 64 * 128; i += nt) {
        int kp = i >> 7, j = i & 127;
        g_Whh_g[i] = bfbits(whh[(256 + j) * 128 + 2 * kp]) |
                     (bfbits(whh[(256 + j) * 128 + 2 * kp + 1]) << 16);
    }
    for (int i = tid; i < 32 * 128; i += nt) {
        int p = i >> 7, j = i & 127;
        g_dr0C[i] = bfbits(d0[j * 89 + 25 + 2 * p]) | (bfbits(d0[j * 89 + 26 + 2 * p]) << 16);
        g_df0C[i] = bfbits(f0[j * 89 + 25 + 2 * p]) | (bfbits(f0[j * 89 + 26 + 2 * p]) << 16);
    }
    for (int i = tid; i < 13 * 128; i += nt) {
        int p = i >> 7, j = i & 127;
        int k0 = 2 * p, k1 = 2 * p + 1;
        float a0 = (k0 < 25) ? d0[j * 89 + k0] : 0.f;
        float a1 = (k1 < 25) ? d0[j * 89 + k1] : 0.f;
        g_dr0D[i] = bfbits(a0) | (bfbits(a1) << 16);
        float c0 = (k0 < 25) ? f0[j * 89 + k0] : 0.f;
        float c1 = (k1 < 25) ? f0[j * 89 + k1] : 0.f;
        g_df0D[i] = bfbits(c0) | (bfbits(c1) << 16);
    }
    for (int i = tid; i < 64 * 128; i += nt) {
        int kp = i >> 7, j = i & 127;
        g_dr1P[i] = bfbits(d1[j * 128 + 2 * kp]) | (bfbits(d1[j * 128 + 2 * kp + 1]) << 16);
        g_dr2P[i] = bfbits(d2[j * 128 + 2 * kp]) | (bfbits(d2[j * 128 + 2 * kp + 1]) << 16);
        g_df1P[i] = bfbits(f1[j * 128 + 2 * kp]) | (bfbits(f1[j * 128 + 2 * kp + 1]) << 16);
    }
    for (int i = tid; i < 15 * 128; i += nt) { int o = i >> 7, k = i & 127; g_dr3T[k * 15 + o] = d3[i]; }
    for (int i = tid; i < 15 * 128; i += nt) { int o = i >> 7, k = i & 127; g_df2T[k * 15 + o] = f2[i]; }
    for (int i = tid; i < 64 * 128; i += nt) { int o = i >> 7, k = i & 127; g_projT[k * 64 + o] = proj[i]; }
}

// ---------------- 5x5 helpers ----------------------------------------------------
__device__ __forceinline__ void mm5(const float* A, const float* Bm, float* Cm) {
#pragma unroll
    for (int i = 0; i < 5; i++) {
#pragma unroll
        for (int jj = 0; jj < 5; jj++) {
            float s = A[i * 5] * Bm[jj];
#pragma unroll
            for (int k = 1; k < 5; k++) s += A[i * 5 + k] * Bm[k * 5 + jj];
            Cm[i * 5 + jj] = s;
        }
    }
}

// base = &inp_s[0][lane]; sigma rows 64..88, coeff rows 90..104, stride PAD
__device__ void geo_update(float* base) {
    const float is2 = 0.70710678118654752f;
    float S[25];
#pragma unroll
    for (int i = 0; i < 25; i++) S[i] = base[(64 + i) * PAD];
    float c[15];
#pragma unroll
    for (int i = 0; i < 15; i++) c[i] = base[(90 + i) * PAD];

    float A[25];
    A[0] = c[0]; A[6] = c[1]; A[12] = c[2]; A[18] = c[3]; A[24] = c[4];
    A[1] = A[5] = c[5] * is2;   A[2] = A[10] = c[6] * is2;
    A[3] = A[15] = c[7] * is2;  A[4] = A[20] = c[8] * is2;
    A[7] = A[11] = c[9] * is2;  A[8] = A[16] = c[10] * is2;
    A[9] = A[21] = c[11] * is2; A[13] = A[17] = c[12] * is2;
    A[14] = A[22] = c[13] * is2; A[19] = A[23] = c[14] * is2;

    float tr = S[0] + S[6] + S[12] + S[18] + S[24];
    float ia = 1.0f / tr;
    float Y[25], Z[25];
#pragma unroll
    for (int i = 0; i < 25; i++) { Y[i] = S[i] * ia; Z[i] = 0.f; }
    Z[0] = Z[6] = Z[12] = Z[18] = Z[24] = 1.f;
    for (int it = 0; it < 12; it++) {
        float P[25]; mm5(Z, Y, P);
        float Tm[25];
#pragma unroll
        for (int i = 0; i < 25; i++) Tm[i] = -0.5f * P[i];
        Tm[0] += 1.5f; Tm[6] += 1.5f; Tm[12] += 1.5f; Tm[18] += 1.5f; Tm[24] += 1.5f;
        float Yn[25], Zn[25];
        mm5(Y, Tm, Yn); mm5(Tm, Z, Zn);
#pragma unroll
        for (int i = 0; i < 25; i++) { Y[i] = Yn[i]; Z[i] = Zn[i]; }
    }
    float sa = sqrtf(tr);
    float L[25];
#pragma unroll
    for (int i = 0; i < 25; i++) L[i] = Y[i] * sa;

    float E[25];
#pragma unroll
    for (int i = 0; i < 25; i++) E[i] = 0.f;
    E[0] = E[6] = E[12] = E[18] = E[24] = 1.f;
#pragma unroll
    for (int k = 8; k >= 1; k--) {
        float AE[25]; mm5(A, E, AE);
        const float invk = 1.0f / (float)k;
#pragma unroll
        for (int i = 0; i < 25; i++) E[i] = AE[i] * invk;
        E[0] += 1.f; E[6] += 1.f; E[12] += 1.f; E[18] += 1.f; E[24] += 1.f;
    }

    float M1[25], M2[25];
    mm5(L, E, M1); mm5(M1, L, M2);
#pragma unroll
    for (int i = 0; i < 5; i++)
#pragma unroll
        for (int jj = 0; jj < 5; jj++)
            base[(64 + i * 5 + jj) * PAD] = 0.5f * (M2[i * 5 + jj] + M2[jj * 5 + i]);
}

// ---------------- MLP layer (64 k-pairs, bf16 weights) ---------------------------
__device__ __forceinline__ void mlp_layer64(const u32* __restrict__ Wp,
                                            const float (*in_s)[PAD], float (*out_s)[PAD],
                                            float bias, int j, int rbase) {
    ull acc[2];
    ull b2 = pack2f(bias);
    acc[0] = b2; acc[1] = b2;
#pragma unroll 4
    for (int kp = 0; kp < 64; kp++) {
        int k = 2 * kp;
        u32 ww = Wp[kp * 128 + j];
        ull w0 = bplo(ww), w1 = bphi(ww);
        ulonglong2 v = *(const ulonglong2*)&in_s[k][rbase];
        ulonglong2 u = *(const ulonglong2*)&in_s[k + 1][rbase];
        fma2(acc[0], w0, v.x); fma2(acc[1], w0, v.y);
        fma2(acc[0], w1, u.x); fma2(acc[1], w1, u.y);
    }
#pragma unroll
    for (int p = 0; p < 2; p++) {
        float2 f = unpack2(acc[p]);
        out_s[j][rbase + 2 * p] = f.x * fsig(f.x);
        out_s[j][rbase + 2 * p + 1] = f.y * fsig(f.y);
    }
}

// L0 dynamic part: 13 pairs over rows 64..89, acc seeded from ctx partials
__device__ __forceinline__ void mlp_layer0(const u32* __restrict__ Wp,
                                           const float (*in_s)[PAD], float (*out_s)[PAD],
                                           const ull* pc, int j, int rbase) {
    ull acc[2];
    acc[0] = pc[0]; acc[1] = pc[1];
#pragma unroll 4
    for (int kp = 0; kp < 13; kp++) {
        int k = 64 + 2 * kp;
        u32 ww = Wp[kp * 128 + j];
        ull w0 = bplo(ww), w1 = bphi(ww);
        ulonglong2 v = *(const ulonglong2*)&in_s[k][rbase];
        ulonglong2 u = *(const ulonglong2*)&in_s[k + 1][rbase];
        fma2(acc[0], w0, v.x); fma2(acc[1], w0, v.y);
        fma2(acc[0], w1, u.x); fma2(acc[1], w1, u.y);
    }
#pragma unroll
    for (int p = 0; p < 2; p++) {
        float2 f = unpack2(acc[p]);
        out_s[j][rbase + 2 * p] = f.x * fsig(f.x);
        out_s[j][rbase + 2 * p + 1] = f.y * fsig(f.y);
    }
}

// ---------------- fused GRU + SDE kernel: 8 rows/block, grid 512 ----------------
// smem pool (12 KB) lifetimes:
//   GRU phase:  h_s = pool[0..1536)    x_s = pool[1536..1848)
//   SDE phase:  b1_s = pool[0..1536)   b2_s = pool[1536..3072)
__global__ void __launch_bounds__(256, 4) fused_kernel(
    const float* __restrict__ C, const float* __restrict__ dW,
    const float* __restrict__ gbias, const float* __restrict__ gbias_n,
    const float* __restrict__ proj_b,
    const float* __restrict__ db0, const float* __restrict__ db1,
    const float* __restrict__ db2, const float* __restrict__ db3,
    const float* __restrict__ fb0, const float* __restrict__ fb1,
    const float* __restrict__ fb2, float* __restrict__ out) {
    __shared__ __align__(16) float pool_s[3072];          // 12 KB shared pool
    __shared__ __align__(16) float inp_s[106][PAD];       // ctx/sigma/coeff (~5 KB)

    float (*h_s)[PAD]  = (float (*)[PAD])pool_s;          // 128 rows (GRU)
    float (*x_s)[PAD]  = (float (*)[PAD])(pool_s + 1536); // 26 rows  (GRU)
    float (*b1_s)[PAD] = (float (*)[PAD])pool_s;          // 128 rows (SDE)
    float (*b2_s)[PAD] = (float (*)[PAD])(pool_s + 1536); // 128 rows (SDE)

    const int tid = threadIdx.x;
    const int b0 = blockIdx.x * RPB;
    const int j = tid & 127, rg = tid >> 7, rbase = rg * 4;

    for (int i = tid; i < 1848; i += 256) pool_s[i] = 0.f;   // h_s + x_s
    if (tid < PAD) inp_s[89][tid] = 0.f;

    const float br = gbias[j], bz = gbias[128 + j], bg = gbias[256 + j], bn = gbias_n[j];
    const ull br2 = pack2f(br), bz2 = pack2f(bz), bg2 = pack2f(bg);

    // ================= GRU encoder =================
    for (int t = 0; t < T_LEN; t++) {
        __syncthreads();
        for (int i = tid; i < RPB * 25; i += 256) {
            int r = i / 25, k = i - r * 25;
            int ii = k / 5, jj = k - ii * 5;
            const float* p = C + ((size_t)(b0 + r) * T_LEN + t) * 25;
            x_s[k][r] = 0.5f * (p[ii * 5 + jj] + p[jj * 5 + ii]);
        }
        __syncthreads();

        ull Ar[2], Az[2], Ag[2], Ah[2];
#pragma unroll
        for (int p = 0; p < 2; p++) { Ar[p] = br2; Az[p] = bz2; Ag[p] = bg2; Ah[p] = 0ull; }

        // input part (13 k-pairs)
#pragma unroll 4
        for (int kp = 0; kp < 13; kp++) {
            int k = 2 * kp;
            u32 rz0 = g_Wih_rz[k * 128 + j];
            u32 rz1 = g_Wih_rz[(k + 1) * 128 + j];
            u32 gg = g_Wih_g[kp * 128 + j];
            ull wr0 = bplo(rz0), wz0 = bphi(rz0), wg0 = bplo(gg);
            ull wr1 = bplo(rz1), wz1 = bphi(rz1), wg1 = bphi(gg);
            ulonglong2 v = *(const ulonglong2*)&x_s[k][rbase];
            ulonglong2 u = *(const ulonglong2*)&x_s[k + 1][rbase];
            fma2(Ar[0], wr0, v.x); fma2(Az[0], wz0, v.x); fma2(Ag[0], wg0, v.x);
            fma2(Ar[1], wr0, v.y); fma2(Az[1], wz0, v.y); fma2(Ag[1], wg0, v.y);
            fma2(Ar[0], wr1, u.x); fma2(Az[0], wz1, u.x); fma2(Ag[0], wg1, u.x);
            fma2(Ar[1], wr1, u.y); fma2(Az[1], wz1, u.y); fma2(Ag[1], wg1, u.y);
        }
        // hidden part (64 k-pairs)
#pragma unroll 4
        for (int kp = 0; kp < 64; kp++) {
            int k = 2 * kp;
            u32 rz0 = g_Whh_rz[k * 128 + j];
            u32 rz1 = g_Whh_rz[(k + 1) * 128 + j];
            u32 gg = g_Whh_g[kp * 128 + j];
            ull wr0 = bplo(rz0), wz0 = bphi(rz0), wg0 = bplo(gg);
            ull wr1 = bplo(rz1), wz1 = bphi(rz1), wg1 = bphi(gg);
            ulonglong2 v = *(const ulonglong2*)&h_s[k][rbase];
            ulonglong2 u = *(const ulonglong2*)&h_s[k + 1][rbase];
            fma2(Ar[0], wr0, v.x); fma2(Az[0], wz0, v.x); fma2(Ah[0], wg0, v.x);
            fma2(Ar[1], wr0, v.y); fma2(Az[1], wz0, v.y); fma2(Ah[1], wg0, v.y);
            fma2(Ar[0], wr1, u.x); fma2(Az[0], wz1, u.x); fma2(Ah[0], wg1, u.x);
            fma2(Ar[1], wr1, u.y); fma2(Az[1], wz1, u.y); fma2(Ah[1], wg1, u.y);
        }

        float hnew[4];
        {
            const ull* hj = (const ull*)&h_s[j][rbase];
#pragma unroll
            for (int p = 0; p < 2; p++) {
                float2 fr = unpack2(Ar[p]), fz = unpack2(Az[p]);
                float2 fg = unpack2(Ag[p]), fh = unpack2(Ah[p]);
                float2 ho = unpack2(hj[p]);
                {
                    float r = fsig(fr.x), z = fsig(fz.x);
                    float g = ftanh(fg.x + r * (fh.x + bn));
                    hnew[2 * p] = (1.f - z) * g + z * ho.x;
                }
                {
                    float r = fsig(fr.y), z = fsig(fz.y);
                    float g = ftanh(fg.y + r * (fh.y + bn));
                    hnew[2 * p + 1] = (1.f - z) * g + z * ho.y;
                }
            }
        }
        __syncthreads();
#pragma unroll
        for (int m = 0; m < 4; m++) h_s[j][rbase + m] = hnew[m];
    }
    __syncthreads();

    // ================= projection: ctx -> inp_s rows 0..63 =================
    {
        const int jc = tid & 63, rg2 = tid >> 6;
        const float pb = proj_b[jc];
#pragma unroll
        for (int m = 0; m < 2; m++) {
            int r = rg2 * 2 + m;
            float acc = pb;
#pragma unroll 4
            for (int k = 0; k < 128; k++) acc += h_s[k][r] * g_projT[k * 64 + jc];
            inp_s[jc][r] = acc;
        }
    }
    // sigma_0 = sym(context[:, T-1]) -> rows 64..88
    for (int i = tid; i < RPB * 25; i += 256) {
        int r = i / 25, k = i - r * 25;
        int ii = k / 5, jj = k - ii * 5;
        const float* p = C + ((size_t)(b0 + r) * T_LEN + (T_LEN - 1)) * 25;
        inp_s[64 + k][r] = 0.5f * (p[ii * 5 + jj] + p[jj * 5 + ii]);
    }
    __syncthreads();   // after this, h_s/x_s dead -> pool reused as b1_s/b2_s

    // ============ precompute ctx partial sums for both L0 layers ============
    ull pc_dr[2], pc_df[2];
    {
        ull bd = pack2f(db0[j]), bf = pack2f(fb0[j]);
        pc_dr[0] = bd; pc_dr[1] = bd; pc_df[0] = bf; pc_df[1] = bf;
#pragma unroll 2
        for (int kp = 0; kp < 32; kp++) {
            int k = 2 * kp;
            u32 wd = g_dr0C[kp * 128 + j];
            u32 wf = g_df0C[kp * 128 + j];
            ull d0w = bplo(wd), d1w = bphi(wd);
            ull f0w = bplo(wf), f1w = bphi(wf);
            ulonglong2 v = *(const ulonglong2*)&inp_s[k][rbase];
            ulonglong2 u = *(const ulonglong2*)&inp_s[k + 1][rbase];
            fma2(pc_dr[0], d0w, v.x); fma2(pc_dr[1], d0w, v.y);
            fma2(pc_dr[0], d1w, u.x); fma2(pc_dr[1], d1w, u.y);
            fma2(pc_df[0], f0w, v.x); fma2(pc_df[1], f0w, v.y);
            fma2(pc_df[0], f1w, u.x); fma2(pc_df[1], f1w, u.y);
        }
    }

    const float v_db1 = db1[j], v_db2 = db2[j];
    const float v_fb1 = fb1[j];

    // ================= SDE steps =================
    for (int step = 0; step < NSTEPS; step++) {
        mlp_layer0(g_dr0D, inp_s, b1_s, pc_dr, j, rbase);
        __syncthreads();
        mlp_layer64(g_dr1P, b1_s, b2_s, v_db1, j, rbase);
        __syncthreads();
        mlp_layer64(g_dr2P, b2_s, b1_s, v_db2, j, rbase);
        __syncthreads();
        // drift L3 (120 items, fp32) + diff L0 (all threads); disjoint smem
        {
            if (tid < RPB * 15) {
                int r = tid / 15, k = tid - r * 15;
                float acc = db3[k];
#pragma unroll 4
                for (int cc = 0; cc < 128; cc++) acc += b1_s[cc][r] * g_dr3T[cc * 15 + k];
                inp_s[90 + k][r] = acc;   // raw drift_c
            }
            mlp_layer0(g_df0D, inp_s, b2_s, pc_df, j, rbase);
        }
        __syncthreads();
        mlp_layer64(g_df1P, b2_s, b1_s, v_fb1, j, rbase);
        __syncthreads();
        // diff L2 + combine: coeff = drift*DT + softplus(.)*dW
        if (tid < RPB * 15) {
            int r = tid / 15, k = tid - r * 15;
            float acc = fb2[k];
#pragma unroll 4
            for (int cc = 0; cc < 128; cc++) acc += b1_s[cc][r] * g_df2T[cc * 15 + k];
            float sp = (acc > 20.f) ? acc : log1pf(__expf(acc));
            float dwv = dW[((size_t)(b0 + r) * NSTEPS + step) * DDIM + k];
            inp_s[90 + k][r] = inp_s[90 + k][r] * DT_C + sp * dwv;
        }
        __syncthreads();
        if (tid < RPB) geo_update(&inp_s[0][tid]);
        __syncthreads();
    }

    for (int i = tid; i < RPB * 25; i += 256) {
        int r = i / 25, k = i - r * 25;
        out[(size_t)(b0 + r) * 25 + k] = inp_s[64 + k][r];
    }
}

// ---------------- launch ---------------------------------------------------------
extern "C" void kernel_launch(void* const* d_in, const int* in_sizes, int n_in,
                              void* d_out, int out_size) {
    const float* ctx_spd = (const float*)d_in[0];
    const float* dWp     = (const float*)d_in[1];
    const float* wih     = (const float*)d_in[2];
    const float* whh     = (const float*)d_in[3];
    const float* gbias   = (const float*)d_in[4];
    const float* gbias_n = (const float*)d_in[5];
    const float* projw   = (const float*)d_in[6];
    const float* projb   = (const float*)d_in[7];
    const float* dw0 = (const float*)d_in[8];  const float* db0 = (const float*)d_in[9];
    const float* dw1 = (const float*)d_in[10]; const float* db1 = (const float*)d_in[11];
    const float* dw2 = (const float*)d_in[12]; const float* db2 = (const float*)d_in[13];
    const float* dw3 = (const float*)d_in[14]; const float* db3 = (const float*)d_in[15];
    const float* fw0 = (const float*)d_in[16]; const float* fb0 = (const float*)d_in[17];
    const float* fw1 = (const float*)d_in[18]; const float* fb1 = (const float*)d_in[19];
    const float* fw2 = (const float*)d_in[20]; const float* fb2 = (const float*)d_in[21];
    float* out = (float*)d_out;

    prep_kernel<<<64, 256>>>(wih, whh, projw, dw0, dw1, dw2, dw3, fw0, fw1, fw2);
    fused_kernel<<<NBLK, 256>>>(ctx_spd, dWp, gbias, gbias_n, projb,
                                db0, db1, db2, db3, fb0, fb1, fb2, out);
}

// round 9
// speedup vs baseline: 1.1540x; 1.1540x over previous
#include <cuda_runtime.h>
#include <cuda_bf16.h>
#include <math.h>

#define B_TOT 4096
#define T_LEN 32
#define DDIM 15
#define NSTEPS 5
#define DT_C 0.2f
#define RPB 16
#define NBLK (B_TOT / RPB)
#define PAD 20

typedef unsigned long long ull;
typedef unsigned int u32;

// ---------------- packed f32x2 helpers ------------------------------------------
__device__ __forceinline__ void fma2(ull& acc, ull a, ull b) {
    asm("fma.rn.f32x2 %0, %1, %2, %0;" : "+l"(acc) : "l"(a), "l"(b));
}
__device__ __forceinline__ ull pack2f(float w) {
    ull r; asm("mov.b64 %0, {%1, %1};" : "=l"(r) : "r"(__float_as_uint(w))); return r;
}
__device__ __forceinline__ ull bplo(u32 u) {
    u32 f = u << 16; ull r; asm("mov.b64 %0, {%1, %1};" : "=l"(r) : "r"(f)); return r;
}
__device__ __forceinline__ ull bphi(u32 u) {
    u32 f = u & 0xFFFF0000u; ull r; asm("mov.b64 %0, {%1, %1};" : "=l"(r) : "r"(f)); return r;
}
__device__ __forceinline__ float2 unpack2(ull v) {
    float2 f; asm("mov.b64 {%0, %1}, %2;" : "=f"(f.x), "=f"(f.y) : "l"(v)); return f;
}
__device__ __forceinline__ float fsig(float x) { return 1.f / (1.f + __expf(-x)); }
__device__ __forceinline__ float ftanh(float x) { return 1.f - 2.f / (1.f + __expf(2.f * x)); }

// ---------------- weight scratch (uint4-packed: 8 k per 16B) --------------------
// u32 index = (kb*2+g4)*512 + j*4 + kk  (rz: k = 8kb+4g4+kk)
// u32 index = kb*512 + j*4 + t          (g / MLP: kp = 4kb+t, k pair = 2kp,2kp+1)
__device__ __align__(16) u32 g_Wih_rz[4096];     // k padded 25->32
__device__ __align__(16) u32 g_Wih_g[2048];
__device__ __align__(16) u32 g_Whh_rz[16384];
__device__ __align__(16) u32 g_Whh_g[8192];
__device__ __align__(16) u32 g_dr0C[4096];       // ctx part, 32 kp
__device__ __align__(16) u32 g_df0C[4096];
__device__ __align__(16) u32 g_dr0D[2048];       // dyn part, 13 kp padded -> 16
__device__ __align__(16) u32 g_df0D[2048];
__device__ __align__(16) u32 g_dr1P[8192];
__device__ __align__(16) u32 g_dr2P[8192];
__device__ __align__(16) u32 g_df1P[8192];
__device__ float g_dr3T[128 * 15];
__device__ float g_df2T[128 * 15];
__device__ float g_projT[128 * 64];

__device__ __forceinline__ u32 bfbits(float w) {
    __nv_bfloat16 h = __float2bfloat16(w);
    return (u32)__bfloat16_as_ushort(h);
}

// ---------------- prep: repack/quantize weights ---------------------------------
__global__ void prep_kernel(const float* __restrict__ wih, const float* __restrict__ whh,
                            const float* __restrict__ proj,
                            const float* __restrict__ d0, const float* __restrict__ d1,
                            const float* __restrict__ d2, const float* __restrict__ d3,
                            const float* __restrict__ f0, const float* __restrict__ f1,
                            const float* __restrict__ f2) {
    int tid = blockIdx.x * blockDim.x + threadIdx.x;
    int nt = gridDim.x * blockDim.x;
    // Wih rz: 4 kb blocks (k 0..31, zero-pad >=25)
    for (int i = tid; i < 4096; i += nt) {
        int kk = i & 3, j = (i >> 2) & 127, g4 = (i >> 9) & 1, kb = i >> 10;
        int k = kb * 8 + g4 * 4 + kk;
        float wr = (k < 25) ? wih[j * 25 + k] : 0.f;
        float wz = (k < 25) ? wih[(128 + j) * 25 + k] : 0.f;
        g_Wih_rz[i] = bfbits(wr) | (bfbits(wz) << 16);
    }
    for (int i = tid; i < 2048; i += nt) {
        int t = i & 3, j = (i >> 2) & 127, kb = i >> 9;
        int kp = kb * 4 + t, k0 = 2 * kp, k1 = 2 * kp + 1;
        float g0 = (k0 < 25) ? wih[(256 + j) * 25 + k0] : 0.f;
        float g1 = (k1 < 25) ? wih[(256 + j) * 25 + k1] : 0.f;
        g_Wih_g[i] = bfbits(g0) | (bfbits(g1) << 16);
    }
    // Whh rz: 16 kb blocks (k 0..127)
    for (int i = tid; i < 16384; i += nt) {
        int kk = i & 3, j = (i >> 2) & 127, g4 = (i >> 9) & 1, kb = i >> 10;
        int k = kb * 8 + g4 * 4 + kk;
        g_Whh_rz[i] = bfbits(whh[j * 128 + k]) | (bfbits(whh[(128 + j) * 128 + k]) << 16);
    }
    for (int i = tid; i < 8192; i += nt) {
        int t = i & 3, j = (i >> 2) & 127, kb = i >> 9;
        int kp = kb * 4 + t;
        g_Whh_g[i] = bfbits(whh[(256 + j) * 128 + 2 * kp]) |
                     (bfbits(whh[(256 + j) * 128 + 2 * kp + 1]) << 16);
    }
    // L0 ctx part: 32 kp (orig input cols 25..88)
    for (int i = tid; i < 4096; i += nt) {
        int t = i & 3, j = (i >> 2) & 127, kb = i >> 9;
        int kp = kb * 4 + t;
        g_dr0C[i] = bfbits(d0[j * 89 + 25 + 2 * kp]) | (bfbits(d0[j * 89 + 26 + 2 * kp]) << 16);
        g_df0C[i] = bfbits(f0[j * 89 + 25 + 2 * kp]) | (bfbits(f0[j * 89 + 26 + 2 * kp]) << 16);
    }
    // L0 dyn part: 16 kp (orig input cols 0..24, zero-pad)
    for (int i = tid; i < 2048; i += nt) {
        int t = i & 3, j = (i >> 2) & 127, kb = i >> 9;
        int kp = kb * 4 + t, k0 = 2 * kp, k1 = 2 * kp + 1;
        float a0 = (k0 < 25) ? d0[j * 89 + k0] : 0.f;
        float a1 = (k1 < 25) ? d0[j * 89 + k1] : 0.f;
        g_dr0D[i] = bfbits(a0) | (bfbits(a1) << 16);
        float c0 = (k0 < 25) ? f0[j * 89 + k0] : 0.f;
        float c1 = (k1 < 25) ? f0[j * 89 + k1] : 0.f;
        g_df0D[i] = bfbits(c0) | (bfbits(c1) << 16);
    }
    // hidden MLP layers: 16 kb blocks
    for (int i = tid; i < 8192; i += nt) {
        int t = i & 3, j = (i >> 2) & 127, kb = i >> 9;
        int kp = kb * 4 + t;
        g_dr1P[i] = bfbits(d1[j * 128 + 2 * kp]) | (bfbits(d1[j * 128 + 2 * kp + 1]) << 16);
        g_dr2P[i] = bfbits(d2[j * 128 + 2 * kp]) | (bfbits(d2[j * 128 + 2 * kp + 1]) << 16);
        g_df1P[i] = bfbits(f1[j * 128 + 2 * kp]) | (bfbits(f1[j * 128 + 2 * kp + 1]) << 16);
    }
    for (int i = tid; i < 15 * 128; i += nt) { int o = i >> 7, k = i & 127; g_dr3T[k * 15 + o] = d3[i]; }
    for (int i = tid; i < 15 * 128; i += nt) { int o = i >> 7, k = i & 127; g_df2T[k * 15 + o] = f2[i]; }
    for (int i = tid; i < 64 * 128; i += nt) { int o = i >> 7, k = i & 127; g_projT[k * 64 + o] = proj[i]; }
}

// ---------------- 5x5 helpers ----------------------------------------------------
__device__ __forceinline__ void mm5(const float* A, const float* Bm, float* Cm) {
#pragma unroll
    for (int i = 0; i < 5; i++) {
#pragma unroll
        for (int jj = 0; jj < 5; jj++) {
            float s = A[i * 5] * Bm[jj];
#pragma unroll
            for (int k = 1; k < 5; k++) s += A[i * 5 + k] * Bm[k * 5 + jj];
            Cm[i * 5 + jj] = s;
        }
    }
}

// base = &inp_s[0][lane]; sigma rows 64..88, coeff rows 90..104, stride PAD
__device__ void geo_update(float* base) {
    const float is2 = 0.70710678118654752f;
    float S[25];
#pragma unroll
    for (int i = 0; i < 25; i++) S[i] = base[(64 + i) * PAD];
    float c[15];
#pragma unroll
    for (int i = 0; i < 15; i++) c[i] = base[(90 + i) * PAD];

    float A[25];
    A[0] = c[0]; A[6] = c[1]; A[12] = c[2]; A[18] = c[3]; A[24] = c[4];
    A[1] = A[5] = c[5] * is2;   A[2] = A[10] = c[6] * is2;
    A[3] = A[15] = c[7] * is2;  A[4] = A[20] = c[8] * is2;
    A[7] = A[11] = c[9] * is2;  A[8] = A[16] = c[10] * is2;
    A[9] = A[21] = c[11] * is2; A[13] = A[17] = c[12] * is2;
    A[14] = A[22] = c[13] * is2; A[19] = A[23] = c[14] * is2;

    float tr = S[0] + S[6] + S[12] + S[18] + S[24];
    float ia = 1.0f / tr;
    float Y[25], Z[25];
#pragma unroll
    for (int i = 0; i < 25; i++) { Y[i] = S[i] * ia; Z[i] = 0.f; }
    Z[0] = Z[6] = Z[12] = Z[18] = Z[24] = 1.f;
    for (int it = 0; it < 12; it++) {
        float P[25]; mm5(Z, Y, P);
        float Tm[25];
#pragma unroll
        for (int i = 0; i < 25; i++) Tm[i] = -0.5f * P[i];
        Tm[0] += 1.5f; Tm[6] += 1.5f; Tm[12] += 1.5f; Tm[18] += 1.5f; Tm[24] += 1.5f;
        float Yn[25], Zn[25];
        mm5(Y, Tm, Yn); mm5(Tm, Z, Zn);
#pragma unroll
        for (int i = 0; i < 25; i++) { Y[i] = Yn[i]; Z[i] = Zn[i]; }
    }
    float sa = sqrtf(tr);
    float L[25];
#pragma unroll
    for (int i = 0; i < 25; i++) L[i] = Y[i] * sa;

    float E[25];
#pragma unroll
    for (int i = 0; i < 25; i++) E[i] = 0.f;
    E[0] = E[6] = E[12] = E[18] = E[24] = 1.f;
#pragma unroll
    for (int k = 8; k >= 1; k--) {
        float AE[25]; mm5(A, E, AE);
        const float invk = 1.0f / (float)k;
#pragma unroll
        for (int i = 0; i < 25; i++) E[i] = AE[i] * invk;
        E[0] += 1.f; E[6] += 1.f; E[12] += 1.f; E[18] += 1.f; E[24] += 1.f;
    }

    float M1[25], M2[25];
    mm5(L, E, M1); mm5(M1, L, M2);
#pragma unroll
    for (int i = 0; i < 5; i++)
#pragma unroll
        for (int jj = 0; jj < 5; jj++)
            base[(64 + i * 5 + jj) * PAD] = 0.5f * (M2[i * 5 + jj] + M2[jj * 5 + i]);
}

// ---------------- pair-processing macros ----------------------------------------
#define GRU_PAIR(RZ0, RZ1, GG, SRC, KK, AH) do { \
    ull wr0 = bplo(RZ0), wz0 = bphi(RZ0), wg0 = bplo(GG); \
    ull wr1 = bplo(RZ1), wz1 = bphi(RZ1), wg1 = bphi(GG); \
    ulonglong2 v0 = *(const ulonglong2*)&SRC[KK][rbase]; \
    ulonglong2 v1 = *(const ulonglong2*)&SRC[KK][rbase + 4]; \
    ulonglong2 u0 = *(const ulonglong2*)&SRC[KK + 1][rbase]; \
    ulonglong2 u1 = *(const ulonglong2*)&SRC[KK + 1][rbase + 4]; \
    fma2(Ar[0], wr0, v0.x); fma2(Az[0], wz0, v0.x); fma2(AH[0], wg0, v0.x); \
    fma2(Ar[1], wr0, v0.y); fma2(Az[1], wz0, v0.y); fma2(AH[1], wg0, v0.y); \
    fma2(Ar[2], wr0, v1.x); fma2(Az[2], wz0, v1.x); fma2(AH[2], wg0, v1.x); \
    fma2(Ar[3], wr0, v1.y); fma2(Az[3], wz0, v1.y); fma2(AH[3], wg0, v1.y); \
    fma2(Ar[0], wr1, u0.x); fma2(Az[0], wz1, u0.x); fma2(AH[0], wg1, u0.x); \
    fma2(Ar[1], wr1, u0.y); fma2(Az[1], wz1, u0.y); fma2(AH[1], wg1, u0.y); \
    fma2(Ar[2], wr1, u1.x); fma2(Az[2], wz1, u1.x); fma2(AH[2], wg1, u1.x); \
    fma2(Ar[3], wr1, u1.y); fma2(Az[3], wz1, u1.y); fma2(AH[3], wg1, u1.y); \
} while (0)

#define MLP_PAIR(WW, IN, KK) do { \
    ull w0 = bplo(WW), w1 = bphi(WW); \
    ulonglong2 v0 = *(const ulonglong2*)&IN[KK][rbase]; \
    ulonglong2 v1 = *(const ulonglong2*)&IN[KK][rbase + 4]; \
    ulonglong2 u0 = *(const ulonglong2*)&IN[KK + 1][rbase]; \
    ulonglong2 u1 = *(const ulonglong2*)&IN[KK + 1][rbase + 4]; \
    fma2(acc[0], w0, v0.x); fma2(acc[1], w0, v0.y); fma2(acc[2], w0, v1.x); fma2(acc[3], w0, v1.y); \
    fma2(acc[0], w1, u0.x); fma2(acc[1], w1, u0.y); fma2(acc[2], w1, u1.x); fma2(acc[3], w1, u1.y); \
} while (0)

#define CTX_PAIR(WD, WF, KK) do { \
    ull d0w = bplo(WD), d1w = bphi(WD); \
    ull f0w = bplo(WF), f1w = bphi(WF); \
    ulonglong2 v0 = *(const ulonglong2*)&inp_s[KK][rbase]; \
    ulonglong2 v1 = *(const ulonglong2*)&inp_s[KK][rbase + 4]; \
    ulonglong2 u0 = *(const ulonglong2*)&inp_s[KK + 1][rbase]; \
    ulonglong2 u1 = *(const ulonglong2*)&inp_s[KK + 1][rbase + 4]; \
    fma2(pc_dr[0], d0w, v0.x); fma2(pc_dr[1], d0w, v0.y); fma2(pc_dr[2], d0w, v1.x); fma2(pc_dr[3], d0w, v1.y); \
    fma2(pc_dr[0], d1w, u0.x); fma2(pc_dr[1], d1w, u0.y); fma2(pc_dr[2], d1w, u1.x); fma2(pc_dr[3], d1w, u1.y); \
    fma2(pc_df[0], f0w, v0.x); fma2(pc_df[1], f0w, v0.y); fma2(pc_df[2], f0w, v1.x); fma2(pc_df[3], f0w, v1.y); \
    fma2(pc_df[0], f1w, u0.x); fma2(pc_df[1], f1w, u0.y); fma2(pc_df[2], f1w, u1.x); fma2(pc_df[3], f1w, u1.y); \
} while (0)

// ---------------- MLP layers (uint4 weight fetch) --------------------------------
__device__ __forceinline__ void mlp_layer64(const u32* __restrict__ Wp,
                                            const float (*in_s)[PAD], float (*out_s)[PAD],
                                            float bias, int j, int rbase) {
    ull acc[4];
    ull b2 = pack2f(bias);
#pragma unroll
    for (int p = 0; p < 4; p++) acc[p] = b2;
#pragma unroll 4
    for (int kb = 0; kb < 16; kb++) {
        uint4 w4 = ((const uint4*)Wp)[kb * 128 + j];
        int k = kb * 8;
        MLP_PAIR(w4.x, in_s, k);
        MLP_PAIR(w4.y, in_s, k + 2);
        MLP_PAIR(w4.z, in_s, k + 4);
        MLP_PAIR(w4.w, in_s, k + 6);
    }
#pragma unroll
    for (int p = 0; p < 4; p++) {
        float2 f = unpack2(acc[p]);
        out_s[j][rbase + 2 * p] = f.x * fsig(f.x);
        out_s[j][rbase + 2 * p + 1] = f.y * fsig(f.y);
    }
}

// L0 dynamic: 16 kp over rows 64..95 (rows 90..95 hit only zero weights)
__device__ __forceinline__ void mlp_layer0(const u32* __restrict__ Wp,
                                           const float (*in_s)[PAD], float (*out_s)[PAD],
                                           const ull* pc, int j, int rbase) {
    ull acc[4];
#pragma unroll
    for (int p = 0; p < 4; p++) acc[p] = pc[p];
#pragma unroll
    for (int kb = 0; kb < 4; kb++) {
        uint4 w4 = ((const uint4*)Wp)[kb * 128 + j];
        int k = 64 + kb * 8;
        MLP_PAIR(w4.x, in_s, k);
        MLP_PAIR(w4.y, in_s, k + 2);
        MLP_PAIR(w4.z, in_s, k + 4);
        MLP_PAIR(w4.w, in_s, k + 6);
    }
#pragma unroll
    for (int p = 0; p < 4; p++) {
        float2 f = unpack2(acc[p]);
        out_s[j][rbase + 2 * p] = f.x * fsig(f.x);
        out_s[j][rbase + 2 * p + 1] = f.y * fsig(f.y);
    }
}

// ---------------- fused GRU + SDE kernel ----------------------------------------
// smem pool (5120 floats):
//   GRU: h_s = pool[0..2560), x_s = pool[2560..3200) (32 rows, 26..31 zero)
//   SDE: b1_s = pool[0..2560), b2_s = pool[2560..5120)
__global__ void __launch_bounds__(256, 2) fused_kernel(
    const float* __restrict__ C, const float* __restrict__ dW,
    const float* __restrict__ gbias, const float* __restrict__ gbias_n,
    const float* __restrict__ proj_b,
    const float* __restrict__ db0, const float* __restrict__ db1,
    const float* __restrict__ db2, const float* __restrict__ db3,
    const float* __restrict__ fb0, const float* __restrict__ fb1,
    const float* __restrict__ fb2, float* __restrict__ out) {
    __shared__ __align__(16) float pool_s[5120];
    // rows: [0..63]=ctx  [64..88]=sigma  [89]=pad  [90..104]=coeff  [105]=pad
    __shared__ __align__(16) float inp_s[106][PAD];

    float (*h_s)[PAD]  = (float (*)[PAD])pool_s;
    float (*x_s)[PAD]  = (float (*)[PAD])(pool_s + 2560);
    float (*b1_s)[PAD] = (float (*)[PAD])pool_s;
    float (*b2_s)[PAD] = (float (*)[PAD])(pool_s + 2560);

    const int tid = threadIdx.x;
    const int b0 = blockIdx.x * RPB;
    const int j = tid & 127, rg = tid >> 7, rbase = rg * 8;

    for (int i = tid; i < 3200; i += 256) pool_s[i] = 0.f;   // h_s + x_s (incl pad rows)
    if (tid < 7 * PAD) (&inp_s[89][0])[tid] = 0.f;           // rows 89..95

    const float br = gbias[j], bz = gbias[128 + j], bg = gbias[256 + j], bn = gbias_n[j];
    const ull br2 = pack2f(br), bz2 = pack2f(bz), bg2 = pack2f(bg);

    // ================= GRU encoder =================
    for (int t = 0; t < T_LEN; t++) {
        __syncthreads();
        for (int i = tid; i < RPB * 25; i += 256) {
            int r = i / 25, k = i - r * 25;
            int ii = k / 5, jj = k - ii * 5;
            const float* p = C + ((size_t)(b0 + r) * T_LEN + t) * 25;
            x_s[k][r] = 0.5f * (p[ii * 5 + jj] + p[jj * 5 + ii]);
        }
        __syncthreads();

        ull Ar[4], Az[4], Ag[4], Ah[4];
#pragma unroll
        for (int p = 0; p < 4; p++) { Ar[p] = br2; Az[p] = bz2; Ag[p] = bg2; Ah[p] = 0ull; }

        // input part: 4 kb blocks (k 0..31, zero-padded)
#pragma unroll 2
        for (int kb = 0; kb < 4; kb++) {
            uint4 rzA = ((const uint4*)g_Wih_rz)[(kb * 2 + 0) * 128 + j];
            uint4 rzB = ((const uint4*)g_Wih_rz)[(kb * 2 + 1) * 128 + j];
            uint4 gg4 = ((const uint4*)g_Wih_g)[kb * 128 + j];
            int k = kb * 8;
            GRU_PAIR(rzA.x, rzA.y, gg4.x, x_s, k, Ag);
            GRU_PAIR(rzA.z, rzA.w, gg4.y, x_s, k + 2, Ag);
            GRU_PAIR(rzB.x, rzB.y, gg4.z, x_s, k + 4, Ag);
            GRU_PAIR(rzB.z, rzB.w, gg4.w, x_s, k + 6, Ag);
        }
        // hidden part: 16 kb blocks (k 0..127)
#pragma unroll 2
        for (int kb = 0; kb < 16; kb++) {
            uint4 rzA = ((const uint4*)g_Whh_rz)[(kb * 2 + 0) * 128 + j];
            uint4 rzB = ((const uint4*)g_Whh_rz)[(kb * 2 + 1) * 128 + j];
            uint4 gg4 = ((const uint4*)g_Whh_g)[kb * 128 + j];
            int k = kb * 8;
            GRU_PAIR(rzA.x, rzA.y, gg4.x, h_s, k, Ah);
            GRU_PAIR(rzA.z, rzA.w, gg4.y, h_s, k + 2, Ah);
            GRU_PAIR(rzB.x, rzB.y, gg4.z, h_s, k + 4, Ah);
            GRU_PAIR(rzB.z, rzB.w, gg4.w, h_s, k + 6, Ah);
        }

        float hnew[8];
        {
            const ull* hj = (const ull*)&h_s[j][rbase];
#pragma unroll
            for (int p = 0; p < 4; p++) {
                float2 fr = unpack2(Ar[p]), fz = unpack2(Az[p]);
                float2 fg = unpack2(Ag[p]), fh = unpack2(Ah[p]);
                float2 ho = unpack2(hj[p]);
                {
                    float r = fsig(fr.x), z = fsig(fz.x);
                    float g = ftanh(fg.x + r * (fh.x + bn));
                    hnew[2 * p] = (1.f - z) * g + z * ho.x;
                }
                {
                    float r = fsig(fr.y), z = fsig(fz.y);
                    float g = ftanh(fg.y + r * (fh.y + bn));
                    hnew[2 * p + 1] = (1.f - z) * g + z * ho.y;
                }
            }
        }
        __syncthreads();
#pragma unroll
        for (int m = 0; m < 8; m++) h_s[j][rbase + m] = hnew[m];
    }
    __syncthreads();

    // ================= projection: ctx -> inp_s rows 0..63 =================
    {
        const int jc = tid & 63, rg2 = tid >> 6;
        const float pb = proj_b[jc];
#pragma unroll
        for (int m = 0; m < 4; m++) {
            int r = rg2 * 4 + m;
            float acc = pb;
#pragma unroll 4
            for (int k = 0; k < 128; k++) acc += h_s[k][r] * g_projT[k * 64 + jc];
            inp_s[jc][r] = acc;
        }
    }
    // sigma_0 = sym(context[:, T-1]) -> rows 64..88
    for (int i = tid; i < RPB * 25; i += 256) {
        int r = i / 25, k = i - r * 25;
        int ii = k / 5, jj = k - ii * 5;
        const float* p = C + ((size_t)(b0 + r) * T_LEN + (T_LEN - 1)) * 25;
        inp_s[64 + k][r] = 0.5f * (p[ii * 5 + jj] + p[jj * 5 + ii]);
    }
    __syncthreads();   // h_s/x_s dead -> pool becomes b1_s/b2_s

    // ============ precompute ctx partial sums for both L0 layers ============
    ull pc_dr[4], pc_df[4];
    {
        ull bd = pack2f(db0[j]), bf = pack2f(fb0[j]);
#pragma unroll
        for (int p = 0; p < 4; p++) { pc_dr[p] = bd; pc_df[p] = bf; }
#pragma unroll 2
        for (int kb = 0; kb < 8; kb++) {
            uint4 wd4 = ((const uint4*)g_dr0C)[kb * 128 + j];
            uint4 wf4 = ((const uint4*)g_df0C)[kb * 128 + j];
            int k = kb * 8;
            CTX_PAIR(wd4.x, wf4.x, k);
            CTX_PAIR(wd4.y, wf4.y, k + 2);
            CTX_PAIR(wd4.z, wf4.z, k + 4);
            CTX_PAIR(wd4.w, wf4.w, k + 6);
        }
    }

    const float v_db1 = db1[j], v_db2 = db2[j];
    const float v_fb1 = fb1[j];

    // ================= SDE steps =================
    for (int step = 0; step < NSTEPS; step++) {
        mlp_layer0(g_dr0D, inp_s, b1_s, pc_dr, j, rbase);
        __syncthreads();
        mlp_layer64(g_dr1P, b1_s, b2_s, v_db1, j, rbase);
        __syncthreads();
        mlp_layer64(g_dr2P, b2_s, b1_s, v_db2, j, rbase);
        __syncthreads();
        // drift L3 (240 items, fp32) + diff L0 (all threads); disjoint smem
        {
            if (tid < 240) {
                int r = tid / 15, k = tid - r * 15;
                float acc = db3[k];
#pragma unroll 4
                for (int cc = 0; cc < 128; cc++) acc += b1_s[cc][r] * g_dr3T[cc * 15 + k];
                inp_s[90 + k][r] = acc;   // raw drift_c
            }
            mlp_layer0(g_df0D, inp_s, b2_s, pc_df, j, rbase);
        }
        __syncthreads();
        mlp_layer64(g_df1P, b2_s, b1_s, v_fb1, j, rbase);
        __syncthreads();
        // diff L2 + combine: coeff = drift*DT + softplus(.)*dW
        if (tid < 240) {
            int r = tid / 15, k = tid - r * 15;
            float acc = fb2[k];
#pragma unroll 4
            for (int cc = 0; cc < 128; cc++) acc += b1_s[cc][r] * g_df2T[cc * 15 + k];
            float sp = (acc > 20.f) ? acc : log1pf(__expf(acc));
            float dwv = dW[((size_t)(b0 + r) * NSTEPS + step) * DDIM + k];
            inp_s[90 + k][r] = inp_s[90 + k][r] * DT_C + sp * dwv;
        }
        __syncthreads();
        if (tid < RPB) geo_update(&inp_s[0][tid]);
        __syncthreads();
    }

    for (int i = tid; i < RPB * 25; i += 256) {
        int r = i / 25, k = i - r * 25;
        out[(size_t)(b0 + r) * 25 + k] = inp_s[64 + k][r];
    }
}

// ---------------- launch ---------------------------------------------------------
extern "C" void kernel_launch(void* const* d_in, const int* in_sizes, int n_in,
                              void* d_out, int out_size) {
    const float* ctx_spd = (const float*)d_in[0];
    const float* dWp     = (const float*)d_in[1];
    const float* wih     = (const float*)d_in[2];
    const float* whh     = (const float*)d_in[3];
    const float* gbias   = (const float*)d_in[4];
    const float* gbias_n = (const float*)d_in[5];
    const float* projw   = (const float*)d_in[6];
    const float* projb   = (const float*)d_in[7];
    const float* dw0 = (const float*)d_in[8];  const float* db0 = (const float*)d_in[9];
    const float* dw1 = (const float*)d_in[10]; const float* db1 = (const float*)d_in[11];
    const float* dw2 = (const float*)d_in[12]; const float* db2 = (const float*)d_in[13];
    const float* dw3 = (const float*)d_in[14]; const float* db3 = (const float*)d_in[15];
    const float* fw0 = (const float*)d_in[16]; const float* fb0 = (const float*)d_in[17];
    const float* fw1 = (const float*)d_in[18]; const float* fb1 = (const float*)d_in[19];
    const float* fw2 = (const float*)d_in[20]; const float* fb2 = (const float*)d_in[21];
    float* out = (float*)d_out;

    prep_kernel<<<64, 256>>>(wih, whh, projw, dw0, dw1, dw2, dw3, fw0, fw1, fw2);
    fused_kernel<<<NBLK, 256>>>(ctx_spd, dWp, gbias, gbias_n, projb,
                                db0, db1, db2, db3, fb0, fb1, fb2, out);
}

// round 12
// speedup vs baseline: 1.9949x; 1.7286x over previous
#include <cuda_runtime.h>
#include <cuda_bf16.h>
#include <math.h>

#define B_TOT 4096
#define T_LEN 32
#define DDIM 15
#define NSTEPS 5
#define DT_C 0.2f
#define RPB 16
#define NBLK (B_TOT / RPB)
#define PAD 20

// GRU mma kernel config
#define GRU_RPB 32
#define GRU_NBLK (B_TOT / GRU_RPB)
#define KS 168                 // padded K stride (elements); 336 B rows
#define KSB 336
#define WOFF 10752             // A region = 32*336 B, then W
#define GRU_SMEM (10752 + 512 * KSB)

typedef unsigned long long ull;
typedef unsigned int u32;
typedef unsigned short u16;

// ---------------- packed f32x2 helpers (SDE path) --------------------------------
__device__ __forceinline__ void fma2(ull& acc, ull a, ull b) {
    asm("fma.rn.f32x2 %0, %1, %2, %0;" : "+l"(acc) : "l"(a), "l"(b));
}
__device__ __forceinline__ ull pack2f(float w) {
    ull r; asm("mov.b64 %0, {%1, %1};" : "=l"(r) : "r"(__float_as_uint(w))); return r;
}
__device__ __forceinline__ ull bplo(u32 u) {
    u32 f = u << 16; ull r; asm("mov.b64 %0, {%1, %1};" : "=l"(r) : "r"(f)); return r;
}
__device__ __forceinline__ ull bphi(u32 u) {
    u32 f = u & 0xFFFF0000u; ull r; asm("mov.b64 %0, {%1, %1};" : "=l"(r) : "r"(f)); return r;
}
__device__ __forceinline__ float2 unpack2(ull v) {
    float2 f; asm("mov.b64 {%0, %1}, %2;" : "=f"(f.x), "=f"(f.y) : "l"(v)); return f;
}
__device__ __forceinline__ float fsig(float x) { return 1.f / (1.f + __expf(-x)); }
__device__ __forceinline__ float ftanh(float x) { return 1.f - 2.f / (1.f + __expf(2.f * x)); }

// ---------------- weight scratch ------------------------------------------------
__device__ __align__(16) u32 g_dr0C[4096];
__device__ __align__(16) u32 g_df0C[4096];
__device__ __align__(16) u32 g_dr0D[2048];
__device__ __align__(16) u32 g_df0D[2048];
__device__ __align__(16) u32 g_dr1P[8192];
__device__ __align__(16) u32 g_dr2P[8192];
__device__ __align__(16) u32 g_df1P[8192];
__device__ float g_dr3T[128 * 15];
__device__ float g_df2T[128 * 15];
__device__ float g_projT[128 * 64];
__device__ float g_ctx[B_TOT * 64];
// GRU unified weight matrix W[512][KS] bf16, row-major (j, k):
//   j 0..127   r  : k<25 = Wih_r, 32<=k<160 = Whh_r
//   j 128..255 z  : same pattern
//   j 256..383 gi : k<25 = Wih_g only
//   j 384..511 gh : 32<=k<160 = Whh_g only
__device__ __align__(16) u16 g_wmma[512 * KS];

__device__ __forceinline__ u32 bfbits(float w) {
    __nv_bfloat16 h = __float2bfloat16(w);
    return (u32)__bfloat16_as_ushort(h);
}
__device__ __forceinline__ u16 bf16u16(float w) {
    __nv_bfloat16 h = __float2bfloat16(w);
    return __bfloat16_as_ushort(h);
}

// ---------------- prep ----------------------------------------------------------
__global__ void prep_kernel(const float* __restrict__ wih, const float* __restrict__ whh,
                            const float* __restrict__ proj,
                            const float* __restrict__ d0, const float* __restrict__ d1,
                            const float* __restrict__ d2, const float* __restrict__ d3,
                            const float* __restrict__ f0, const float* __restrict__ f1,
                            const float* __restrict__ f2) {
    int tid = blockIdx.x * blockDim.x + threadIdx.x;
    int nt = gridDim.x * blockDim.x;

    // unified GRU weight matrix
    for (int i = tid; i < 512 * KS; i += nt) {
        int j = i / KS, k = i - j * KS;
        int g = j >> 7, jj = j & 127;
        float v = 0.f;
        if (g == 0) {
            if (k < 25) v = wih[jj * 25 + k];
            else if (k >= 32 && k < 160) v = whh[jj * 128 + (k - 32)];
        } else if (g == 1) {
            if (k < 25) v = wih[(128 + jj) * 25 + k];
            else if (k >= 32 && k < 160) v = whh[(128 + jj) * 128 + (k - 32)];
        } else if (g == 2) {
            if (k < 25) v = wih[(256 + jj) * 25 + k];
        } else {
            if (k >= 32 && k < 160) v = whh[(256 + jj) * 128 + (k - 32)];
        }
        g_wmma[i] = bf16u16(v);
    }

    // ---- SDE weights (proven R9 packing) ----
    for (int i = tid; i < 4096; i += nt) {
        int t = i & 3, j = (i >> 2) & 127, kb = i >> 9;
        int kp = kb * 4 + t;
        g_dr0C[i] = bfbits(d0[j * 89 + 25 + 2 * kp]) | (bfbits(d0[j * 89 + 26 + 2 * kp]) << 16);
        g_df0C[i] = bfbits(f0[j * 89 + 25 + 2 * kp]) | (bfbits(f0[j * 89 + 26 + 2 * kp]) << 16);
    }
    for (int i = tid; i < 2048; i += nt) {
        int t = i & 3, j = (i >> 2) & 127, kb = i >> 9;
        int kp = kb * 4 + t, k0 = 2 * kp, k1 = 2 * kp + 1;
        float a0 = (k0 < 25) ? d0[j * 89 + k0] : 0.f;
        float a1 = (k1 < 25) ? d0[j * 89 + k1] : 0.f;
        g_dr0D[i] = bfbits(a0) | (bfbits(a1) << 16);
        float c0 = (k0 < 25) ? f0[j * 89 + k0] : 0.f;
        float c1 = (k1 < 25) ? f0[j * 89 + k1] : 0.f;
        g_df0D[i] = bfbits(c0) | (bfbits(c1) << 16);
    }
    for (int i = tid; i < 8192; i += nt) {
        int t = i & 3, j = (i >> 2) & 127, kb = i >> 9;
        int kp = kb * 4 + t;
        g_dr1P[i] = bfbits(d1[j * 128 + 2 * kp]) | (bfbits(d1[j * 128 + 2 * kp + 1]) << 16);
        g_dr2P[i] = bfbits(d2[j * 128 + 2 * kp]) | (bfbits(d2[j * 128 + 2 * kp + 1]) << 16);
        g_df1P[i] = bfbits(f1[j * 128 + 2 * kp]) | (bfbits(f1[j * 128 + 2 * kp + 1]) << 16);
    }
    for (int i = tid; i < 15 * 128; i += nt) { int o = i >> 7, k = i & 127; g_dr3T[k * 15 + o] = d3[i]; }
    for (int i = tid; i < 15 * 128; i += nt) { int o = i >> 7, k = i & 127; g_df2T[k * 15 + o] = f2[i]; }
    for (int i = tid; i < 64 * 128; i += nt) { int o = i >> 7, k = i & 127; g_projT[k * 64 + o] = proj[i]; }
}

// ---------------- mma helpers ----------------------------------------------------
__device__ __forceinline__ u32 smem_u32(const void* p) {
    u32 a;
    asm("{ .reg .u64 t; cvta.to.shared.u64 t, %1; cvt.u32.u64 %0, t; }" : "=r"(a) : "l"(p));
    return a;
}

#define LDSM4(R0, R1, R2, R3, ADDR) \
    asm volatile("ldmatrix.sync.aligned.m8n8.x4.shared.b16 {%0,%1,%2,%3}, [%4];" \
        : "=r"(R0), "=r"(R1), "=r"(R2), "=r"(R3) : "r"(ADDR))

#define MMA16816(CACC, B0, B1) \
    asm volatile("mma.sync.aligned.m16n8k16.row.col.f32.bf16.bf16.f32 " \
        "{%0,%1,%2,%3}, {%4,%5,%6,%7}, {%8,%9}, {%0,%1,%2,%3};" \
        : "+f"((CACC)[0]), "+f"((CACC)[1]), "+f"((CACC)[2]), "+f"((CACC)[3]) \
        : "r"(fa0), "r"(fa1), "r"(fa2), "r"(fa3), "r"(B0), "r"(B1))

// ---------------- GRU mma.sync kernel: 128 CTAs x 256 thr, 32 rows --------------
// Fragment layouts (PTX ISA, m16n8k16 row.col):
//   A a0..a3: a0=(m=l/4,   k=(l%4)*2+{0,1}) a1=(m+8, same k) a2=(m, k+8) a3=(m+8, k+8)
//   B b0,b1:  b0=(k=(l%4)*2+{0,1}, n=l/4)   b1=(k+8, n)  [= W[n][k] pairs, k contiguous]
//   C c0..c3: c0=(m=l/4, n=(l%4)*2) c1=(m, n+1) c2=(m+8, n) c3=(m+8, n+1)
// ldmatrix x4: lanegroup q (lanes 8q..8q+7) supplies row addrs of tile q; lane l
// receives tile-element (row=l/4, colpair=(l%4)*2) of each tile in r0..r3.
__global__ void __launch_bounds__(256, 1)
gru_mma_kernel(const float* __restrict__ C,
               const float* __restrict__ gbias, const float* __restrict__ gbias_n,
               const float* __restrict__ proj_b) {
    extern __shared__ __align__(16) char sm[];
    const u32 smb = smem_u32(sm);

    const int tid = threadIdx.x;
    const int b0 = blockIdx.x * GRU_RPB;
    const int wid = tid >> 5, lane = tid & 31;
    const int rg = wid >> 2;          // row group (0..1): rows rg*16..+15
    const int jq = wid & 3;           // j quarter: j0..j0+31 of each gate
    const int j0 = jq * 32;

    // stage W: 512*336 B = 10752 uint4
    {
        const uint4* src = (const uint4*)g_wmma;
        uint4* dst = (uint4*)(sm + WOFF);
        for (int i = tid; i < 10752; i += 256) dst[i] = src[i];
    }
    // zero A (32*336 = 672 uint4): x pad cols 25..31 stay 0; h (k>=32) starts 0
    {
        uint4 z = make_uint4(0, 0, 0, 0);
        uint4* dst = (uint4*)sm;
        for (int i = tid; i < 672; i += 256) dst[i] = z;
    }
    __syncthreads();

    // per-lane ldmatrix invariants
    const int rowA = (lane & 7) + ((lane >> 3) & 1) * 8;     // lanes 0-15 rows, 16-31 repeat
    const u32 aBase = smb + (rg * 16 + rowA) * KSB + (((lane >> 4) & 1) * 8) * 2;
    const int rowB = (lane & 7) + ((lane >> 4) & 1) * 8;     // lanes 16-31 -> +8 (2nd n-tile)
    const u32 bBase = smb + WOFF + (j0 + rowB) * KSB + (((lane >> 3) & 1) * 8) * 2;

    // per-lane epilogue biases: j = j0 + q*8 + (lane%4)*2
    float bR[4][2], bZ[4][2], bG[4][2], bN[4][2];
#pragma unroll
    for (int q = 0; q < 4; q++) {
        int j = j0 + q * 8 + (lane & 3) * 2;
        bR[q][0] = gbias[j];        bR[q][1] = gbias[j + 1];
        bZ[q][0] = gbias[128 + j];  bZ[q][1] = gbias[129 + j];
        bG[q][0] = gbias[256 + j];  bG[q][1] = gbias[257 + j];
        bN[q][0] = gbias_n[j];      bN[q][1] = gbias_n[j + 1];
    }

    for (int t = 0; t < T_LEN; t++) {
        // ---- stage X_t (sym, bf16) into A[m][k<25] ----
        for (int i = tid; i < GRU_RPB * 25; i += 256) {
            int r = i / 25, k = i - r * 25;
            int ii = k / 5, jj = k - ii * 5;
            const float* p = C + ((size_t)(b0 + r) * T_LEN + t) * 25;
            float v = 0.5f * (p[ii * 5 + jj] + p[jj * 5 + ii]);
            *(u16*)(sm + r * KSB + k * 2) = bf16u16(v);
        }
        __syncthreads();

        // ---- mainloop: acc[g*4+q'][4], q' = n-tile within 32-j quarter ----
        float acc[16][4];
#pragma unroll
        for (int i = 0; i < 16; i++) {
            acc[i][0] = 0.f; acc[i][1] = 0.f; acc[i][2] = 0.f; acc[i][3] = 0.f;
        }
        for (int kt = 0; kt < 10; kt++) {
            u32 fa0, fa1, fa2, fa3;
            LDSM4(fa0, fa1, fa2, fa3, aBase + kt * 32);
#pragma unroll
            for (int g = 0; g < 4; g++) {
#pragma unroll
                for (int p = 0; p < 2; p++) {
                    u32 fb0, fb1, fb2, fb3;
                    LDSM4(fb0, fb1, fb2, fb3,
                          bBase + (u32)(g * 128 + p * 16) * KSB + kt * 32);
                    MMA16816(acc[g * 4 + 2 * p], fb0, fb1);
                    MMA16816(acc[g * 4 + 2 * p + 1], fb2, fb3);
                }
            }
        }

        // ---- epilogue: gates + h update ----
#pragma unroll
        for (int q = 0; q < 4; q++) {
            const float* aR = acc[0 * 4 + q];
            const float* aZ = acc[1 * 4 + q];
            const float* aGI = acc[2 * 4 + q];
            const float* aGH = acc[3 * 4 + q];
            int jc = j0 + q * 8 + (lane & 3) * 2;
#pragma unroll
            for (int half = 0; half < 2; half++) {
                int row = rg * 16 + (lane >> 2) + half * 8;
                u32* hptr = (u32*)(sm + row * KSB + (32 + jc) * 2);
                u32 hold = *hptr;
                float ho0 = __uint_as_float((hold & 0xFFFFu) << 16);
                float ho1 = __uint_as_float(hold & 0xFFFF0000u);
                int c = half * 2;
                float r0 = fsig(aR[c] + bR[q][0]);
                float r1 = fsig(aR[c + 1] + bR[q][1]);
                float z0 = fsig(aZ[c] + bZ[q][0]);
                float z1 = fsig(aZ[c + 1] + bZ[q][1]);
                float g0 = ftanh(aGI[c] + bG[q][0] + r0 * (aGH[c] + bN[q][0]));
                float g1 = ftanh(aGI[c + 1] + bG[q][1] + r1 * (aGH[c + 1] + bN[q][1]));
                float h0 = (1.f - z0) * g0 + z0 * ho0;
                float h1 = (1.f - z1) * g1 + z1 * ho1;
                *hptr = (u32)bf16u16(h0) | ((u32)bf16u16(h1) << 16);
            }
        }
        __syncthreads();
    }

    // ---- projection: ctx = h @ proj^T + proj_b -> g_ctx ----
    {
        const int jc = tid & 63, rq = tid >> 6;
        for (int m = 0; m < 8; m++) {
            int r = rq * 8 + m;
            const u16* hrow = (const u16*)(sm + r * KSB + 64);   // k=32 elem offset
            float acc = proj_b[jc];
#pragma unroll 4
            for (int k = 0; k < 128; k++) {
                float hv = __uint_as_float(((u32)hrow[k]) << 16);
                acc += hv * g_projT[k * 64 + jc];
            }
            g_ctx[(size_t)(b0 + r) * 64 + jc] = acc;
        }
    }
}

// ---------------- 5x5 helpers ----------------------------------------------------
__device__ __forceinline__ void mm5(const float* A, const float* Bm, float* Cm) {
#pragma unroll
    for (int i = 0; i < 5; i++) {
#pragma unroll
        for (int jj = 0; jj < 5; jj++) {
            float s = A[i * 5] * Bm[jj];
#pragma unroll
            for (int k = 1; k < 5; k++) s += A[i * 5 + k] * Bm[k * 5 + jj];
            Cm[i * 5 + jj] = s;
        }
    }
}

__device__ void geo_update(float* base) {
    const float is2 = 0.70710678118654752f;
    float S[25];
#pragma unroll
    for (int i = 0; i < 25; i++) S[i] = base[(64 + i) * PAD];
    float c[15];
#pragma unroll
    for (int i = 0; i < 15; i++) c[i] = base[(90 + i) * PAD];

    float A[25];
    A[0] = c[0]; A[6] = c[1]; A[12] = c[2]; A[18] = c[3]; A[24] = c[4];
    A[1] = A[5] = c[5] * is2;   A[2] = A[10] = c[6] * is2;
    A[3] = A[15] = c[7] * is2;  A[4] = A[20] = c[8] * is2;
    A[7] = A[11] = c[9] * is2;  A[8] = A[16] = c[10] * is2;
    A[9] = A[21] = c[11] * is2; A[13] = A[17] = c[12] * is2;
    A[14] = A[22] = c[13] * is2; A[19] = A[23] = c[14] * is2;

    float tr = S[0] + S[6] + S[12] + S[18] + S[24];
    float ia = 1.0f / tr;
    float Y[25], Z[25];
#pragma unroll
    for (int i = 0; i < 25; i++) { Y[i] = S[i] * ia; Z[i] = 0.f; }
    Z[0] = Z[6] = Z[12] = Z[18] = Z[24] = 1.f;
    for (int it = 0; it < 12; it++) {
        float P[25]; mm5(Z, Y, P);
        float Tm[25];
#pragma unroll
        for (int i = 0; i < 25; i++) Tm[i] = -0.5f * P[i];
        Tm[0] += 1.5f; Tm[6] += 1.5f; Tm[12] += 1.5f; Tm[18] += 1.5f; Tm[24] += 1.5f;
        float Yn[25], Zn[25];
        mm5(Y, Tm, Yn); mm5(Tm, Z, Zn);
#pragma unroll
        for (int i = 0; i < 25; i++) { Y[i] = Yn[i]; Z[i] = Zn[i]; }
    }
    float sa = sqrtf(tr);
    float L[25];
#pragma unroll
    for (int i = 0; i < 25; i++) L[i] = Y[i] * sa;

    float E[25];
#pragma unroll
    for (int i = 0; i < 25; i++) E[i] = 0.f;
    E[0] = E[6] = E[12] = E[18] = E[24] = 1.f;
#pragma unroll
    for (int k = 8; k >= 1; k--) {
        float AE[25]; mm5(A, E, AE);
        const float invk = 1.0f / (float)k;
#pragma unroll
        for (int i = 0; i < 25; i++) E[i] = AE[i] * invk;
        E[0] += 1.f; E[6] += 1.f; E[12] += 1.f; E[18] += 1.f; E[24] += 1.f;
    }

    float M1[25], M2[25];
    mm5(L, E, M1); mm5(M1, L, M2);
#pragma unroll
    for (int i = 0; i < 5; i++)
#pragma unroll
        for (int jj = 0; jj < 5; jj++)
            base[(64 + i * 5 + jj) * PAD] = 0.5f * (M2[i * 5 + jj] + M2[jj * 5 + i]);
}

// ---------------- SDE pair macros (R9) -------------------------------------------
#define MLP_PAIR(WW, IN, KK) do { \
    ull w0 = bplo(WW), w1 = bphi(WW); \
    ulonglong2 v0 = *(const ulonglong2*)&IN[KK][rbase]; \
    ulonglong2 v1 = *(const ulonglong2*)&IN[KK][rbase + 4]; \
    ulonglong2 u0 = *(const ulonglong2*)&IN[KK + 1][rbase]; \
    ulonglong2 u1 = *(const ulonglong2*)&IN[KK + 1][rbase + 4]; \
    fma2(acc[0], w0, v0.x); fma2(acc[1], w0, v0.y); fma2(acc[2], w0, v1.x); fma2(acc[3], w0, v1.y); \
    fma2(acc[0], w1, u0.x); fma2(acc[1], w1, u0.y); fma2(acc[2], w1, u1.x); fma2(acc[3], w1, u1.y); \
} while (0)

#define CTX_PAIR(WD, WF, KK) do { \
    ull d0w = bplo(WD), d1w = bphi(WD); \
    ull f0w = bplo(WF), f1w = bphi(WF); \
    ulonglong2 v0 = *(const ulonglong2*)&inp_s[KK][rbase]; \
    ulonglong2 v1 = *(const ulonglong2*)&inp_s[KK][rbase + 4]; \
    ulonglong2 u0 = *(const ulonglong2*)&inp_s[KK + 1][rbase]; \
    ulonglong2 u1 = *(const ulonglong2*)&inp_s[KK + 1][rbase + 4]; \
    fma2(pc_dr[0], d0w, v0.x); fma2(pc_dr[1], d0w, v0.y); fma2(pc_dr[2], d0w, v1.x); fma2(pc_dr[3], d0w, v1.y); \
    fma2(pc_dr[0], d1w, u0.x); fma2(pc_dr[1], d1w, u0.y); fma2(pc_dr[2], d1w, u1.x); fma2(pc_dr[3], d1w, u1.y); \
    fma2(pc_df[0], f0w, v0.x); fma2(pc_df[1], f0w, v0.y); fma2(pc_df[2], f0w, v1.x); fma2(pc_df[3], f0w, v1.y); \
    fma2(pc_df[0], f1w, u0.x); fma2(pc_df[1], f1w, u0.y); fma2(pc_df[2], f1w, u1.x); fma2(pc_df[3], f1w, u1.y); \
} while (0)

__device__ __forceinline__ void mlp_layer64(const u32* __restrict__ Wp,
                                            const float (*in_s)[PAD], float (*out_s)[PAD],
                                            float bias, int j, int rbase) {
    ull acc[4];
    ull b2 = pack2f(bias);
#pragma unroll
    for (int p = 0; p < 4; p++) acc[p] = b2;
#pragma unroll 4
    for (int kb = 0; kb < 16; kb++) {
        uint4 w4 = ((const uint4*)Wp)[kb * 128 + j];
        int k = kb * 8;
        MLP_PAIR(w4.x, in_s, k);
        MLP_PAIR(w4.y, in_s, k + 2);
        MLP_PAIR(w4.z, in_s, k + 4);
        MLP_PAIR(w4.w, in_s, k + 6);
    }
#pragma unroll
    for (int p = 0; p < 4; p++) {
        float2 f = unpack2(acc[p]);
        out_s[j][rbase + 2 * p] = f.x * fsig(f.x);
        out_s[j][rbase + 2 * p + 1] = f.y * fsig(f.y);
    }
}

__device__ __forceinline__ void mlp_layer0(const u32* __restrict__ Wp,
                                           const float (*in_s)[PAD], float (*out_s)[PAD],
                                           const ull* pc, int j, int rbase) {
    ull acc[4];
#pragma unroll
    for (int p = 0; p < 4; p++) acc[p] = pc[p];
#pragma unroll
    for (int kb = 0; kb < 4; kb++) {
        uint4 w4 = ((const uint4*)Wp)[kb * 128 + j];
        int k = 64 + kb * 8;
        MLP_PAIR(w4.x, in_s, k);
        MLP_PAIR(w4.y, in_s, k + 2);
        MLP_PAIR(w4.z, in_s, k + 4);
        MLP_PAIR(w4.w, in_s, k + 6);
    }
#pragma unroll
    for (int p = 0; p < 4; p++) {
        float2 f = unpack2(acc[p]);
        out_s[j][rbase + 2 * p] = f.x * fsig(f.x);
        out_s[j][rbase + 2 * p + 1] = f.y * fsig(f.y);
    }
}

// ---------------- SDE kernel (R9 logic, ctx from g_ctx) --------------------------
__global__ void __launch_bounds__(256, 2) sde_kernel(
    const float* __restrict__ C, const float* __restrict__ dW,
    const float* __restrict__ db0, const float* __restrict__ db1,
    const float* __restrict__ db2, const float* __restrict__ db3,
    const float* __restrict__ fb0, const float* __restrict__ fb1,
    const float* __restrict__ fb2, float* __restrict__ out) {
    __shared__ __align__(16) float pool_s[5120];
    __shared__ __align__(16) float inp_s[106][PAD];

    float (*b1_s)[PAD] = (float (*)[PAD])pool_s;
    float (*b2_s)[PAD] = (float (*)[PAD])(pool_s + 2560);

    const int tid = threadIdx.x;
    const int b0 = blockIdx.x * RPB;
    const int j = tid & 127, rg = tid >> 7, rbase = rg * 8;

    for (int i = tid; i < RPB * 64; i += 256) {
        int r = i >> 6, k = i & 63;
        inp_s[k][r] = g_ctx[(size_t)(b0 + r) * 64 + k];
    }
    if (tid < 7 * PAD) (&inp_s[89][0])[tid] = 0.f;
    for (int i = tid; i < RPB * 25; i += 256) {
        int r = i / 25, k = i - r * 25;
        int ii = k / 5, jj = k - ii * 5;
        const float* p = C + ((size_t)(b0 + r) * T_LEN + (T_LEN - 1)) * 25;
        inp_s[64 + k][r] = 0.5f * (p[ii * 5 + jj] + p[jj * 5 + ii]);
    }
    __syncthreads();

    ull pc_dr[4], pc_df[4];
    {
        ull bd = pack2f(db0[j]), bf = pack2f(fb0[j]);
#pragma unroll
        for (int p = 0; p < 4; p++) { pc_dr[p] = bd; pc_df[p] = bf; }
#pragma unroll 2
        for (int kb = 0; kb < 8; kb++) {
            uint4 wd4 = ((const uint4*)g_dr0C)[kb * 128 + j];
            uint4 wf4 = ((const uint4*)g_df0C)[kb * 128 + j];
            int k = kb * 8;
            CTX_PAIR(wd4.x, wf4.x, k);
            CTX_PAIR(wd4.y, wf4.y, k + 2);
            CTX_PAIR(wd4.z, wf4.z, k + 4);
            CTX_PAIR(wd4.w, wf4.w, k + 6);
        }
    }

    const float v_db1 = db1[j], v_db2 = db2[j];
    const float v_fb1 = fb1[j];

    for (int step = 0; step < NSTEPS; step++) {
        mlp_layer0(g_dr0D, inp_s, b1_s, pc_dr, j, rbase);
        __syncthreads();
        mlp_layer64(g_dr1P, b1_s, b2_s, v_db1, j, rbase);
        __syncthreads();
        mlp_layer64(g_dr2P, b2_s, b1_s, v_db2, j, rbase);
        __syncthreads();
        {
            if (tid < 240) {
                int r = tid / 15, k = tid - r * 15;
                float acc = db3[k];
#pragma unroll 4
                for (int cc = 0; cc < 128; cc++) acc += b1_s[cc][r] * g_dr3T[cc * 15 + k];
                inp_s[90 + k][r] = acc;
            }
            mlp_layer0(g_df0D, inp_s, b2_s, pc_df, j, rbase);
        }
        __syncthreads();
        mlp_layer64(g_df1P, b2_s, b1_s, v_fb1, j, rbase);
        __syncthreads();
        if (tid < 240) {
            int r = tid / 15, k = tid - r * 15;
            float acc = fb2[k];
#pragma unroll 4
            for (int cc = 0; cc < 128; cc++) acc += b1_s[cc][r] * g_df2T[cc * 15 + k];
            float sp = (acc > 20.f) ? acc : log1pf(__expf(acc));
            float dwv = dW[((size_t)(b0 + r) * NSTEPS + step) * DDIM + k];
            inp_s[90 + k][r] = inp_s[90 + k][r] * DT_C + sp * dwv;
        }
        __syncthreads();
        if (tid < RPB) geo_update(&inp_s[0][tid]);
        __syncthreads();
    }

    for (int i = tid; i < RPB * 25; i += 256) {
        int r = i / 25, k = i - r * 25;
        out[(size_t)(b0 + r) * 25 + k] = inp_s[64 + k][r];
    }
}

// ---------------- launch ---------------------------------------------------------
extern "C" void kernel_launch(void* const* d_in, const int* in_sizes, int n_in,
                              void* d_out, int out_size) {
    const float* ctx_spd = (const float*)d_in[0];
    const float* dWp     = (const float*)d_in[1];
    const float* wih     = (const float*)d_in[2];
    const float* whh     = (const float*)d_in[3];
    const float* gbias   = (const float*)d_in[4];
    const float* gbias_n = (const float*)d_in[5];
    const float* projw   = (const float*)d_in[6];
    const float* projb   = (const float*)d_in[7];
    const float* dw0 = (const float*)d_in[8];  const float* db0 = (const float*)d_in[9];
    const float* dw1 = (const float*)d_in[10]; const float* db1 = (const float*)d_in[11];
    const float* dw2 = (const float*)d_in[12]; const float* db2 = (const float*)d_in[13];
    const float* dw3 = (const float*)d_in[14]; const float* db3 = (const float*)d_in[15];
    const float* fw0 = (const float*)d_in[16]; const float* fb0 = (const float*)d_in[17];
    const float* fw1 = (const float*)d_in[18]; const float* fb1 = (const float*)d_in[19];
    const float* fw2 = (const float*)d_in[20]; const float* fb2 = (const float*)d_in[21];
    float* out = (float*)d_out;

    static int smem_set = 0;
    if (!smem_set) {
        cudaFuncSetAttribute(gru_mma_kernel, cudaFuncAttributeMaxDynamicSharedMemorySize, GRU_SMEM);
        smem_set = 1;
    }

    prep_kernel<<<64, 256>>>(wih, whh, projw, dw0, dw1, dw2, dw3, fw0, fw1, fw2);
    gru_mma_kernel<<<GRU_NBLK, 256, GRU_SMEM>>>(ctx_spd, gbias, gbias_n, projb);
    sde_kernel<<<NBLK, 256>>>(ctx_spd, dWp, db0, db1, db2, db3, fb0, fb1, fb2, out);
}